// round 8
// baseline (speedup 1.0000x reference)
#include <cuda_runtime.h>

#define C   128
#define C4  32
#define NODES_MAX 100000
#define EDGES_MAX 1600000

typedef unsigned long long u64;

// ---- scratch (allocation-free rule: static __device__ arrays) --------------
__device__ float g_agg [(size_t)NODES_MAX * C];
__device__ float g_h1  [(size_t)NODES_MAX * C];
__device__ float g_h2  [(size_t)NODES_MAX * C];
__device__ int   g_cnt [NODES_MAX];
__device__ int   g_off [NODES_MAX + 1];
__device__ int   g_fill[NODES_MAX];
__device__ int   g_ssrc[EDGES_MAX];
__device__ int   g_bsum[128];

// ---- packed fp32x2 helpers (sm_103a FFMA2) ---------------------------------
__device__ __forceinline__ u64 pk(float lo, float hi) {
    u64 r; asm("mov.b64 %0, {%1, %2};" : "=l"(r) : "f"(lo), "f"(hi)); return r;
}
__device__ __forceinline__ u64 pk1(float v) { return pk(v, v); }
__device__ __forceinline__ u64 ffma2(u64 a, u64 b, u64 c) {
    u64 d; asm("fma.rn.f32x2 %0, %1, %2, %3;" : "=l"(d) : "l"(a), "l"(b), "l"(c));
    return d;
}
__device__ __forceinline__ float2 upk(u64 v) {
    float2 r; asm("mov.b64 {%0, %1}, %2;" : "=f"(r.x), "=f"(r.y) : "l"(v)); return r;
}

// ---------------------------------------------------------------------------
// Degree histogram pipeline: clear -> hist -> 3-step exclusive scan -> sort
// ---------------------------------------------------------------------------
__global__ void clear_cnt_kernel(int n) {
    int i = blockIdx.x * blockDim.x + threadIdx.x;
    if (i < n) g_cnt[i] = 0;
}

__global__ void deg_kernel(const int* __restrict__ dst, int E) {
    int i = blockIdx.x * blockDim.x + threadIdx.x;
    if (i < E) atomicAdd(&g_cnt[dst[i]], 1);
}

// scan step 1: per-block (1024 counts) sums
__global__ void scan1_kernel(int n) {
    __shared__ int wsum[8];
    int b = blockIdx.x, tid = threadIdx.x;
    int i = b * 1024 + tid * 4;
    int s = 0;
    #pragma unroll
    for (int j = 0; j < 4; j++) if (i + j < n) s += g_cnt[i + j];
    #pragma unroll
    for (int o = 16; o > 0; o >>= 1) s += __shfl_down_sync(0xffffffffu, s, o);
    if ((tid & 31) == 0) wsum[tid >> 5] = s;
    __syncthreads();
    if (tid == 0) {
        int t = 0;
        #pragma unroll
        for (int k = 0; k < 8; k++) t += wsum[k];
        g_bsum[b] = t;
    }
}

// scan step 2: exclusive scan of <=128 block sums (single block)
__global__ void scan2_kernel(int nb, int n) {
    __shared__ int sm_[128];
    int tid = threadIdx.x;
    int v = (tid < nb) ? g_bsum[tid] : 0;
    sm_[tid] = v;
    __syncthreads();
    #pragma unroll
    for (int o = 1; o < 128; o <<= 1) {
        int t = (tid >= o) ? sm_[tid - o] : 0;
        __syncthreads();
        sm_[tid] += t;
        __syncthreads();
    }
    if (tid < nb) g_bsum[tid] = sm_[tid] - v;   // exclusive
    if (tid == 127) g_off[n] = sm_[127];        // total = E
}

// scan step 3: full exclusive scan; writes g_off and g_fill
__global__ void scan3_kernel(int n) {
    __shared__ int wsum[8];
    int b = blockIdx.x, tid = threadIdx.x;
    int lane = tid & 31, w = tid >> 5;
    int i = b * 1024 + tid * 4;
    int c[4];
    #pragma unroll
    for (int j = 0; j < 4; j++) c[j] = (i + j < n) ? g_cnt[i + j] : 0;
    int tsum = c[0] + c[1] + c[2] + c[3];
    int v = tsum;
    #pragma unroll
    for (int o = 1; o < 32; o <<= 1) {
        int t = __shfl_up_sync(0xffffffffu, v, o);
        if (lane >= o) v += t;
    }
    if (lane == 31) wsum[w] = v;
    __syncthreads();
    if (tid == 0) {
        int r = 0;
        #pragma unroll
        for (int k = 0; k < 8; k++) { int t = wsum[k]; wsum[k] = r; r += t; }
    }
    __syncthreads();
    int excl = g_bsum[b] + wsum[w] + (v - tsum);
    #pragma unroll
    for (int j = 0; j < 4; j++) {
        if (i + j < n) { g_off[i + j] = excl; g_fill[i + j] = excl; }
        excl += c[j];
    }
}

// bucket edges by destination (order within bucket irrelevant for the sum)
__global__ void sort_kernel(const int* __restrict__ src,
                            const int* __restrict__ dst, int E) {
    int e = blockIdx.x * blockDim.x + threadIdx.x;
    if (e < E) {
        int pos = atomicAdd(&g_fill[dst[e]], 1);
        g_ssrc[pos] = src[e];
    }
}

// ---------------------------------------------------------------------------
// Segment mean-aggregation: one warp per node, register accumulation.
// Replaces zero + red.global scatter: 819MB L2 RMW -> 51MB streamed write.
// ---------------------------------------------------------------------------
__global__ void agg_kernel(const float* __restrict__ h, int n) {
    int node = (blockIdx.x * blockDim.x + threadIdx.x) >> 5;
    int lane = threadIdx.x & 31;
    if (node >= n) return;
    int beg = g_off[node], end = g_off[node + 1];
    const float4* h4 = reinterpret_cast<const float4*>(h);
    float4 acc = make_float4(0.f, 0.f, 0.f, 0.f);
    for (int p = beg; p < end; p += 32) {
        int m = min(32, end - p);
        int s = (lane < m) ? __ldg(g_ssrc + p + lane) : 0;
        #pragma unroll 4
        for (int j = 0; j < m; j++) {
            int sj = __shfl_sync(0xffffffffu, s, j);
            float4 v = __ldg(h4 + (size_t)sj * C4 + lane);
            acc.x += v.x; acc.y += v.y; acc.z += v.z; acc.w += v.w;
        }
    }
    float iv = 1.0f / (float)max(end - beg, 1);
    acc.x *= iv; acc.y *= iv; acc.z *= iv; acc.w *= iv;
    reinterpret_cast<float4*>(g_agg)[(size_t)node * C4 + lane] = acc;
}

// ---------------------------------------------------------------------------
// Fused SAGE dense layer with packed FFMA2:
//   out[n,:] = relu( mean[n,:] @ Wl + in[n,:] @ Wr + bias )
// 64-node tile/block; thread = 8 nodes x 4 cols. Weights in smem, pre-packed
// as u64 col-pair planes (conflict-free LDS.64, no pack ops in the mainloop).
// ---------------------------------------------------------------------------
__global__ void __launch_bounds__(256, 1)
sage_kernel(const float* __restrict__ in,  const float* __restrict__ Wl,
            const float* __restrict__ Wr,  const float* __restrict__ bias,
            float* __restrict__ out, int n)
{
    extern __shared__ char smraw[];
    u64*    sWlA = reinterpret_cast<u64*>(smraw);      // [128k][32c4] cols {0,1}
    u64*    sWlB = sWlA + 4096;                        // cols {2,3}
    u64*    sWrA = sWlB + 4096;
    u64*    sWrB = sWrA + 4096;                        // 128KB weights
    float4* sA   = reinterpret_cast<float4*>(sWrB + 4096); // 64x32 mean
    float4* sB   = sA + 2048;                          // 64x32 root  (+64KB)

    const int tid = threadIdx.x;
    const float4* Wl4 = reinterpret_cast<const float4*>(Wl);
    const float4* Wr4 = reinterpret_cast<const float4*>(Wr);
    #pragma unroll 4
    for (int i = tid; i < 4096; i += 256) {
        float4 l = __ldg(Wl4 + i), r = __ldg(Wr4 + i);
        sWlA[i] = pk(l.x, l.y); sWlB[i] = pk(l.z, l.w);
        sWrA[i] = pk(r.x, r.y); sWrB[i] = pk(r.z, r.w);
    }

    const int n0 = blockIdx.x * 64;
    const float4* agg4 = reinterpret_cast<const float4*>(g_agg);
    const float4* in4  = reinterpret_cast<const float4*>(in);
    #pragma unroll 2
    for (int i = tid; i < 2048; i += 256) {
        int node = n0 + (i >> 5);
        float4 a = make_float4(0.f, 0.f, 0.f, 0.f), b = a;
        if (node < n) {
            a = agg4[(size_t)node * C4 + (i & 31)];
            b = __ldg(in4 + (size_t)node * C4 + (i & 31));
        }
        sA[i] = a; sB[i] = b;
    }
    __syncthreads();

    const int col4 = tid & 31;
    const int nb   = (tid >> 5) * 8;

    u64 acc[8][2];
    #pragma unroll
    for (int m = 0; m < 8; m++) { acc[m][0] = 0ull; acc[m][1] = 0ull; }

    #pragma unroll 2
    for (int k4 = 0; k4 < 32; k4++) {
        float a_[8][4], b_[8][4];
        #pragma unroll
        for (int m = 0; m < 8; m++) {
            *reinterpret_cast<float4*>(a_[m]) = sA[(nb + m) * 32 + k4];
            *reinterpret_cast<float4*>(b_[m]) = sB[(nb + m) * 32 + k4];
        }
        #pragma unroll
        for (int kk = 0; kk < 4; kk++) {
            int k = k4 * 4 + kk;
            u64 wlA = sWlA[k * 32 + col4], wlB = sWlB[k * 32 + col4];
            u64 wrA = sWrA[k * 32 + col4], wrB = sWrB[k * 32 + col4];
            #pragma unroll
            for (int m = 0; m < 8; m++) {
                u64 av = pk1(a_[m][kk]);
                u64 bv = pk1(b_[m][kk]);
                acc[m][0] = ffma2(av, wlA, acc[m][0]);
                acc[m][0] = ffma2(bv, wrA, acc[m][0]);
                acc[m][1] = ffma2(av, wlB, acc[m][1]);
                acc[m][1] = ffma2(bv, wrB, acc[m][1]);
            }
        }
    }

    float4 bq = __ldg(reinterpret_cast<const float4*>(bias) + col4);
    float4* out4 = reinterpret_cast<float4*>(out);
    #pragma unroll
    for (int m = 0; m < 8; m++) {
        int node = n0 + nb + m;
        if (node < n) {
            float2 p0 = upk(acc[m][0]), p1 = upk(acc[m][1]);
            float4 r;
            r.x = fmaxf(p0.x + bq.x, 0.f);
            r.y = fmaxf(p0.y + bq.y, 0.f);
            r.z = fmaxf(p1.x + bq.z, 0.f);
            r.w = fmaxf(p1.y + bq.w, 0.f);
            out4[(size_t)node * C4 + col4] = r;
        }
    }
}

// ---------------------------------------------------------------------------
// Decoder + residual with packed FFMA2:
//   out[n,:] = alpha * (h2[n,:] @ Wd + bd) + (1-alpha) * x[n,:]
// ---------------------------------------------------------------------------
__global__ void __launch_bounds__(256, 1)
dec_kernel(const float* __restrict__ x, const float* __restrict__ Wd,
           const float* __restrict__ bd, const float* __restrict__ alpha_p,
           float* __restrict__ out, int n)
{
    extern __shared__ char smraw[];
    u64*    sWA = reinterpret_cast<u64*>(smraw);   // 4096
    u64*    sWB = sWA + 4096;                      // 4096 (64KB)
    float4* sB  = reinterpret_cast<float4*>(sWB + 4096); // 2048 (32KB)

    const int tid = threadIdx.x;
    const float4* W4 = reinterpret_cast<const float4*>(Wd);
    #pragma unroll 4
    for (int i = tid; i < 4096; i += 256) {
        float4 w = __ldg(W4 + i);
        sWA[i] = pk(w.x, w.y); sWB[i] = pk(w.z, w.w);
    }

    const int n0 = blockIdx.x * 64;
    const float4* h4 = reinterpret_cast<const float4*>(g_h2);
    #pragma unroll 2
    for (int i = tid; i < 2048; i += 256) {
        int node = n0 + (i >> 5);
        sB[i] = (node < n) ? h4[(size_t)node * C4 + (i & 31)]
                           : make_float4(0.f, 0.f, 0.f, 0.f);
    }
    __syncthreads();

    const int col4 = tid & 31;
    const int nb   = (tid >> 5) * 8;

    u64 acc[8][2];
    #pragma unroll
    for (int m = 0; m < 8; m++) { acc[m][0] = 0ull; acc[m][1] = 0ull; }

    #pragma unroll 2
    for (int k4 = 0; k4 < 32; k4++) {
        float b_[8][4];
        #pragma unroll
        for (int m = 0; m < 8; m++)
            *reinterpret_cast<float4*>(b_[m]) = sB[(nb + m) * 32 + k4];
        #pragma unroll
        for (int kk = 0; kk < 4; kk++) {
            int k = k4 * 4 + kk;
            u64 wA = sWA[k * 32 + col4], wB = sWB[k * 32 + col4];
            #pragma unroll
            for (int m = 0; m < 8; m++) {
                u64 bv = pk1(b_[m][kk]);
                acc[m][0] = ffma2(bv, wA, acc[m][0]);
                acc[m][1] = ffma2(bv, wB, acc[m][1]);
            }
        }
    }

    float alpha = __ldg(alpha_p);
    float beta  = 1.0f - alpha;
    float4 bq = __ldg(reinterpret_cast<const float4*>(bd) + col4);
    const float4* x4 = reinterpret_cast<const float4*>(x);
    float4* out4 = reinterpret_cast<float4*>(out);
    #pragma unroll
    for (int m = 0; m < 8; m++) {
        int node = n0 + nb + m;
        if (node < n) {
            float2 p0 = upk(acc[m][0]), p1 = upk(acc[m][1]);
            float4 xv = __ldg(x4 + (size_t)node * C4 + col4);
            float4 r;
            r.x = alpha * (p0.x + bq.x) + beta * xv.x;
            r.y = alpha * (p0.y + bq.y) + beta * xv.y;
            r.z = alpha * (p1.x + bq.z) + beta * xv.z;
            r.w = alpha * (p1.y + bq.w) + beta * xv.w;
            out4[(size_t)node * C4 + col4] = r;
        }
    }
}

// ---------------------------------------------------------------------------
// Host launcher
// ---------------------------------------------------------------------------
extern "C" void kernel_launch(void* const* d_in, const int* in_sizes, int n_in,
                              void* d_out, int out_size)
{
    const float* x   = (const float*)d_in[0];
    const int*   ei  = (const int*)  d_in[1];
    const float* W1l = (const float*)d_in[2];
    const float* b1  = (const float*)d_in[3];
    const float* W1r = (const float*)d_in[4];
    const float* W2l = (const float*)d_in[5];
    const float* b2  = (const float*)d_in[6];
    const float* W2r = (const float*)d_in[7];
    const float* Wd  = (const float*)d_in[8];
    const float* bd  = (const float*)d_in[9];
    const float* al  = (const float*)d_in[10];
    float* out = (float*)d_out;

    const int n = in_sizes[0] / C;
    const int E = in_sizes[1] / 2;
    const int* src = ei;
    const int* dst = ei + E;

    float *h1p = nullptr, *h2p = nullptr;
    cudaGetSymbolAddress((void**)&h1p, g_h1);
    cudaGetSymbolAddress((void**)&h2p, g_h2);

    const int SAGE_SMEM = 16384 * (int)sizeof(u64) + 4096 * (int)sizeof(float4); // 196608
    const int DEC_SMEM  =  8192 * (int)sizeof(u64) + 2048 * (int)sizeof(float4); //  98304
    cudaFuncSetAttribute(sage_kernel, cudaFuncAttributeMaxDynamicSharedMemorySize, SAGE_SMEM);
    cudaFuncSetAttribute(dec_kernel,  cudaFuncAttributeMaxDynamicSharedMemorySize, DEC_SMEM);

    const int nb1   = (n + 1023) / 1024;          // scan blocks (98 for 100K)
    const int egrid = (E + 255) / 256;
    const int agrid = (n * 32 + 255) / 256;       // warp per node
    const int sgrid = (n + 63) / 64;              // 64-node tiles

    // Edge bucketing by dst (built once, used by both layers)
    clear_cnt_kernel<<<(n + 255) / 256, 256>>>(n);
    deg_kernel<<<egrid, 256>>>(dst, E);
    scan1_kernel<<<nb1, 256>>>(n);
    scan2_kernel<<<1, 128>>>(nb1, n);
    scan3_kernel<<<nb1, 256>>>(n);
    sort_kernel<<<egrid, 256>>>(src, dst, E);

    // Layer 1
    agg_kernel<<<agrid, 256>>>(x, n);
    sage_kernel<<<sgrid, 256, SAGE_SMEM>>>(x, W1l, W1r, b1, h1p, n);

    // Layer 2
    agg_kernel<<<agrid, 256>>>(h1p, n);
    sage_kernel<<<sgrid, 256, SAGE_SMEM>>>(h1p, W2l, W2r, b2, h2p, n);

    // Decoder + residual
    dec_kernel<<<sgrid, 256, DEC_SMEM>>>(x, Wd, bd, al, out, n);
}

// round 9
// speedup vs baseline: 1.0021x; 1.0021x over previous
#include <cuda_runtime.h>

#define C   128
#define C4  32
#define NODES_MAX 100000
#define EDGES_MAX 1600000

typedef unsigned long long u64;

// ---- scratch (allocation-free rule: static __device__ arrays) --------------
__device__ float g_agg [(size_t)NODES_MAX * C];
__device__ float g_h1  [(size_t)NODES_MAX * C];
__device__ float g_h2  [(size_t)NODES_MAX * C];
__device__ int   g_cnt [NODES_MAX];
__device__ int   g_off [NODES_MAX + 1];
__device__ int   g_fill[NODES_MAX];
__device__ int   g_ssrc[EDGES_MAX];
__device__ int   g_bsum[128];

// ---- packed fp32x2 helpers (sm_103a FFMA2) ---------------------------------
__device__ __forceinline__ u64 pk(float lo, float hi) {
    u64 r; asm("mov.b64 %0, {%1, %2};" : "=l"(r) : "f"(lo), "f"(hi)); return r;
}
__device__ __forceinline__ u64 pk1(float v) { return pk(v, v); }
__device__ __forceinline__ u64 ffma2(u64 a, u64 b, u64 c) {
    u64 d; asm("fma.rn.f32x2 %0, %1, %2, %3;" : "=l"(d) : "l"(a), "l"(b), "l"(c));
    return d;
}
__device__ __forceinline__ float2 upk(u64 v) {
    float2 r; asm("mov.b64 {%0, %1}, %2;" : "=f"(r.x), "=f"(r.y) : "l"(v)); return r;
}

// ---------------------------------------------------------------------------
// Degree histogram pipeline: clear -> hist -> 3-step exclusive scan -> sort
// ---------------------------------------------------------------------------
__global__ void clear_cnt_kernel(int n) {
    int i = blockIdx.x * blockDim.x + threadIdx.x;
    if (i < n) g_cnt[i] = 0;
}

__global__ void deg_kernel(const int* __restrict__ dst, int E) {
    int i = blockIdx.x * blockDim.x + threadIdx.x;
    if (i < E) atomicAdd(&g_cnt[dst[i]], 1);
}

// scan step 1: per-block (1024 counts) sums
__global__ void scan1_kernel(int n) {
    __shared__ int wsum[8];
    int b = blockIdx.x, tid = threadIdx.x;
    int i = b * 1024 + tid * 4;
    int s = 0;
    #pragma unroll
    for (int j = 0; j < 4; j++) if (i + j < n) s += g_cnt[i + j];
    #pragma unroll
    for (int o = 16; o > 0; o >>= 1) s += __shfl_down_sync(0xffffffffu, s, o);
    if ((tid & 31) == 0) wsum[tid >> 5] = s;
    __syncthreads();
    if (tid == 0) {
        int t = 0;
        #pragma unroll
        for (int k = 0; k < 8; k++) t += wsum[k];
        g_bsum[b] = t;
    }
}

// scan step 2: exclusive scan of <=128 block sums (single block)
__global__ void scan2_kernel(int nb, int n) {
    __shared__ int sm_[128];
    int tid = threadIdx.x;
    int v = (tid < nb) ? g_bsum[tid] : 0;
    sm_[tid] = v;
    __syncthreads();
    #pragma unroll
    for (int o = 1; o < 128; o <<= 1) {
        int t = (tid >= o) ? sm_[tid - o] : 0;
        __syncthreads();
        sm_[tid] += t;
        __syncthreads();
    }
    if (tid < nb) g_bsum[tid] = sm_[tid] - v;   // exclusive
    if (tid == 127) g_off[n] = sm_[127];        // total = E
}

// scan step 3: full exclusive scan; writes g_off and g_fill
__global__ void scan3_kernel(int n) {
    __shared__ int wsum[8];
    int b = blockIdx.x, tid = threadIdx.x;
    int lane = tid & 31, w = tid >> 5;
    int i = b * 1024 + tid * 4;
    int c[4];
    #pragma unroll
    for (int j = 0; j < 4; j++) c[j] = (i + j < n) ? g_cnt[i + j] : 0;
    int tsum = c[0] + c[1] + c[2] + c[3];
    int v = tsum;
    #pragma unroll
    for (int o = 1; o < 32; o <<= 1) {
        int t = __shfl_up_sync(0xffffffffu, v, o);
        if (lane >= o) v += t;
    }
    if (lane == 31) wsum[w] = v;
    __syncthreads();
    if (tid == 0) {
        int r = 0;
        #pragma unroll
        for (int k = 0; k < 8; k++) { int t = wsum[k]; wsum[k] = r; r += t; }
    }
    __syncthreads();
    int excl = g_bsum[b] + wsum[w] + (v - tsum);
    #pragma unroll
    for (int j = 0; j < 4; j++) {
        if (i + j < n) { g_off[i + j] = excl; g_fill[i + j] = excl; }
        excl += c[j];
    }
}

// bucket edges by destination (order within bucket irrelevant for the sum)
__global__ void sort_kernel(const int* __restrict__ src,
                            const int* __restrict__ dst, int E) {
    int e = blockIdx.x * blockDim.x + threadIdx.x;
    if (e < E) {
        int pos = atomicAdd(&g_fill[dst[e]], 1);
        g_ssrc[pos] = src[e];
    }
}

// ---------------------------------------------------------------------------
// Segment mean-aggregation: one warp per node, register accumulation.
// Replaces zero + red.global scatter: 819MB L2 RMW -> 51MB streamed write.
// ---------------------------------------------------------------------------
__global__ void agg_kernel(const float* __restrict__ h, int n) {
    int node = (blockIdx.x * blockDim.x + threadIdx.x) >> 5;
    int lane = threadIdx.x & 31;
    if (node >= n) return;
    int beg = g_off[node], end = g_off[node + 1];
    const float4* h4 = reinterpret_cast<const float4*>(h);
    float4 acc = make_float4(0.f, 0.f, 0.f, 0.f);
    for (int p = beg; p < end; p += 32) {
        int m = min(32, end - p);
        int s = (lane < m) ? __ldg(g_ssrc + p + lane) : 0;
        #pragma unroll 4
        for (int j = 0; j < m; j++) {
            int sj = __shfl_sync(0xffffffffu, s, j);
            float4 v = __ldg(h4 + (size_t)sj * C4 + lane);
            acc.x += v.x; acc.y += v.y; acc.z += v.z; acc.w += v.w;
        }
    }
    float iv = 1.0f / (float)max(end - beg, 1);
    acc.x *= iv; acc.y *= iv; acc.z *= iv; acc.w *= iv;
    reinterpret_cast<float4*>(g_agg)[(size_t)node * C4 + lane] = acc;
}

// ---------------------------------------------------------------------------
// Fused SAGE dense layer with packed FFMA2:
//   out[n,:] = relu( mean[n,:] @ Wl + in[n,:] @ Wr + bias )
// 64-node tile/block; thread = 8 nodes x 4 cols. Weights in smem, pre-packed
// as u64 col-pair planes (conflict-free LDS.64, no pack ops in the mainloop).
// ---------------------------------------------------------------------------
__global__ void __launch_bounds__(256, 1)
sage_kernel(const float* __restrict__ in,  const float* __restrict__ Wl,
            const float* __restrict__ Wr,  const float* __restrict__ bias,
            float* __restrict__ out, int n)
{
    extern __shared__ char smraw[];
    u64*    sWlA = reinterpret_cast<u64*>(smraw);      // [128k][32c4] cols {0,1}
    u64*    sWlB = sWlA + 4096;                        // cols {2,3}
    u64*    sWrA = sWlB + 4096;
    u64*    sWrB = sWrA + 4096;                        // 128KB weights
    float4* sA   = reinterpret_cast<float4*>(sWrB + 4096); // 64x32 mean
    float4* sB   = sA + 2048;                          // 64x32 root  (+64KB)

    const int tid = threadIdx.x;
    const float4* Wl4 = reinterpret_cast<const float4*>(Wl);
    const float4* Wr4 = reinterpret_cast<const float4*>(Wr);
    #pragma unroll 4
    for (int i = tid; i < 4096; i += 256) {
        float4 l = __ldg(Wl4 + i), r = __ldg(Wr4 + i);
        sWlA[i] = pk(l.x, l.y); sWlB[i] = pk(l.z, l.w);
        sWrA[i] = pk(r.x, r.y); sWrB[i] = pk(r.z, r.w);
    }

    const int n0 = blockIdx.x * 64;
    const float4* agg4 = reinterpret_cast<const float4*>(g_agg);
    const float4* in4  = reinterpret_cast<const float4*>(in);
    #pragma unroll 2
    for (int i = tid; i < 2048; i += 256) {
        int node = n0 + (i >> 5);
        float4 a = make_float4(0.f, 0.f, 0.f, 0.f), b = a;
        if (node < n) {
            a = agg4[(size_t)node * C4 + (i & 31)];
            b = __ldg(in4 + (size_t)node * C4 + (i & 31));
        }
        sA[i] = a; sB[i] = b;
    }
    __syncthreads();

    const int col4 = tid & 31;
    const int nb   = (tid >> 5) * 8;

    u64 acc[8][2];
    #pragma unroll
    for (int m = 0; m < 8; m++) { acc[m][0] = 0ull; acc[m][1] = 0ull; }

    #pragma unroll 2
    for (int k4 = 0; k4 < 32; k4++) {
        float a_[8][4], b_[8][4];
        #pragma unroll
        for (int m = 0; m < 8; m++) {
            *reinterpret_cast<float4*>(a_[m]) = sA[(nb + m) * 32 + k4];
            *reinterpret_cast<float4*>(b_[m]) = sB[(nb + m) * 32 + k4];
        }
        #pragma unroll
        for (int kk = 0; kk < 4; kk++) {
            int k = k4 * 4 + kk;
            u64 wlA = sWlA[k * 32 + col4], wlB = sWlB[k * 32 + col4];
            u64 wrA = sWrA[k * 32 + col4], wrB = sWrB[k * 32 + col4];
            #pragma unroll
            for (int m = 0; m < 8; m++) {
                u64 av = pk1(a_[m][kk]);
                u64 bv = pk1(b_[m][kk]);
                acc[m][0] = ffma2(av, wlA, acc[m][0]);
                acc[m][0] = ffma2(bv, wrA, acc[m][0]);
                acc[m][1] = ffma2(av, wlB, acc[m][1]);
                acc[m][1] = ffma2(bv, wrB, acc[m][1]);
            }
        }
    }

    float4 bq = __ldg(reinterpret_cast<const float4*>(bias) + col4);
    float4* out4 = reinterpret_cast<float4*>(out);
    #pragma unroll
    for (int m = 0; m < 8; m++) {
        int node = n0 + nb + m;
        if (node < n) {
            float2 p0 = upk(acc[m][0]), p1 = upk(acc[m][1]);
            float4 r;
            r.x = fmaxf(p0.x + bq.x, 0.f);
            r.y = fmaxf(p0.y + bq.y, 0.f);
            r.z = fmaxf(p1.x + bq.z, 0.f);
            r.w = fmaxf(p1.y + bq.w, 0.f);
            out4[(size_t)node * C4 + col4] = r;
        }
    }
}

// ---------------------------------------------------------------------------
// Decoder + residual with packed FFMA2:
//   out[n,:] = alpha * (h2[n,:] @ Wd + bd) + (1-alpha) * x[n,:]
// ---------------------------------------------------------------------------
__global__ void __launch_bounds__(256, 1)
dec_kernel(const float* __restrict__ x, const float* __restrict__ Wd,
           const float* __restrict__ bd, const float* __restrict__ alpha_p,
           float* __restrict__ out, int n)
{
    extern __shared__ char smraw[];
    u64*    sWA = reinterpret_cast<u64*>(smraw);   // 4096
    u64*    sWB = sWA + 4096;                      // 4096 (64KB)
    float4* sB  = reinterpret_cast<float4*>(sWB + 4096); // 2048 (32KB)

    const int tid = threadIdx.x;
    const float4* W4 = reinterpret_cast<const float4*>(Wd);
    #pragma unroll 4
    for (int i = tid; i < 4096; i += 256) {
        float4 w = __ldg(W4 + i);
        sWA[i] = pk(w.x, w.y); sWB[i] = pk(w.z, w.w);
    }

    const int n0 = blockIdx.x * 64;
    const float4* h4 = reinterpret_cast<const float4*>(g_h2);
    #pragma unroll 2
    for (int i = tid; i < 2048; i += 256) {
        int node = n0 + (i >> 5);
        sB[i] = (node < n) ? h4[(size_t)node * C4 + (i & 31)]
                           : make_float4(0.f, 0.f, 0.f, 0.f);
    }
    __syncthreads();

    const int col4 = tid & 31;
    const int nb   = (tid >> 5) * 8;

    u64 acc[8][2];
    #pragma unroll
    for (int m = 0; m < 8; m++) { acc[m][0] = 0ull; acc[m][1] = 0ull; }

    #pragma unroll 2
    for (int k4 = 0; k4 < 32; k4++) {
        float b_[8][4];
        #pragma unroll
        for (int m = 0; m < 8; m++)
            *reinterpret_cast<float4*>(b_[m]) = sB[(nb + m) * 32 + k4];
        #pragma unroll
        for (int kk = 0; kk < 4; kk++) {
            int k = k4 * 4 + kk;
            u64 wA = sWA[k * 32 + col4], wB = sWB[k * 32 + col4];
            #pragma unroll
            for (int m = 0; m < 8; m++) {
                u64 bv = pk1(b_[m][kk]);
                acc[m][0] = ffma2(bv, wA, acc[m][0]);
                acc[m][1] = ffma2(bv, wB, acc[m][1]);
            }
        }
    }

    float alpha = __ldg(alpha_p);
    float beta  = 1.0f - alpha;
    float4 bq = __ldg(reinterpret_cast<const float4*>(bd) + col4);
    const float4* x4 = reinterpret_cast<const float4*>(x);
    float4* out4 = reinterpret_cast<float4*>(out);
    #pragma unroll
    for (int m = 0; m < 8; m++) {
        int node = n0 + nb + m;
        if (node < n) {
            float2 p0 = upk(acc[m][0]), p1 = upk(acc[m][1]);
            float4 xv = __ldg(x4 + (size_t)node * C4 + col4);
            float4 r;
            r.x = alpha * (p0.x + bq.x) + beta * xv.x;
            r.y = alpha * (p0.y + bq.y) + beta * xv.y;
            r.z = alpha * (p1.x + bq.z) + beta * xv.z;
            r.w = alpha * (p1.y + bq.w) + beta * xv.w;
            out4[(size_t)node * C4 + col4] = r;
        }
    }
}

// ---------------------------------------------------------------------------
// Host launcher
// ---------------------------------------------------------------------------
extern "C" void kernel_launch(void* const* d_in, const int* in_sizes, int n_in,
                              void* d_out, int out_size)
{
    const float* x   = (const float*)d_in[0];
    const int*   ei  = (const int*)  d_in[1];
    const float* W1l = (const float*)d_in[2];
    const float* b1  = (const float*)d_in[3];
    const float* W1r = (const float*)d_in[4];
    const float* W2l = (const float*)d_in[5];
    const float* b2  = (const float*)d_in[6];
    const float* W2r = (const float*)d_in[7];
    const float* Wd  = (const float*)d_in[8];
    const float* bd  = (const float*)d_in[9];
    const float* al  = (const float*)d_in[10];
    float* out = (float*)d_out;

    const int n = in_sizes[0] / C;
    const int E = in_sizes[1] / 2;
    const int* src = ei;
    const int* dst = ei + E;

    float *h1p = nullptr, *h2p = nullptr;
    cudaGetSymbolAddress((void**)&h1p, g_h1);
    cudaGetSymbolAddress((void**)&h2p, g_h2);

    const int SAGE_SMEM = 16384 * (int)sizeof(u64) + 4096 * (int)sizeof(float4); // 196608
    const int DEC_SMEM  =  8192 * (int)sizeof(u64) + 2048 * (int)sizeof(float4); //  98304
    cudaFuncSetAttribute(sage_kernel, cudaFuncAttributeMaxDynamicSharedMemorySize, SAGE_SMEM);
    cudaFuncSetAttribute(dec_kernel,  cudaFuncAttributeMaxDynamicSharedMemorySize, DEC_SMEM);

    const int nb1   = (n + 1023) / 1024;          // scan blocks (98 for 100K)
    const int egrid = (E + 255) / 256;
    const int agrid = (n * 32 + 255) / 256;       // warp per node
    const int sgrid = (n + 63) / 64;              // 64-node tiles

    // Edge bucketing by dst (built once, used by both layers)
    clear_cnt_kernel<<<(n + 255) / 256, 256>>>(n);
    deg_kernel<<<egrid, 256>>>(dst, E);
    scan1_kernel<<<nb1, 256>>>(n);
    scan2_kernel<<<1, 128>>>(nb1, n);
    scan3_kernel<<<nb1, 256>>>(n);
    sort_kernel<<<egrid, 256>>>(src, dst, E);

    // Layer 1
    agg_kernel<<<agrid, 256>>>(x, n);
    sage_kernel<<<sgrid, 256, SAGE_SMEM>>>(x, W1l, W1r, b1, h1p, n);

    // Layer 2
    agg_kernel<<<agrid, 256>>>(h1p, n);
    sage_kernel<<<sgrid, 256, SAGE_SMEM>>>(h1p, W2l, W2r, b2, h2p, n);

    // Decoder + residual
    dec_kernel<<<sgrid, 256, DEC_SMEM>>>(x, Wd, bd, al, out, n);
}

// round 10
// speedup vs baseline: 1.0027x; 1.0007x over previous
#include <cuda_runtime.h>

#define C   128
#define C4  32
#define NODES_MAX 100000
#define EDGES_MAX 1600000

typedef unsigned long long u64;

// ---- scratch (allocation-free rule: static __device__ arrays) --------------
__device__ float g_agg [(size_t)NODES_MAX * C];
__device__ float g_h1  [(size_t)NODES_MAX * C];
__device__ float g_h2  [(size_t)NODES_MAX * C];
__device__ int   g_cnt [NODES_MAX];
__device__ int   g_off [NODES_MAX + 1];
__device__ int   g_fill[NODES_MAX];
__device__ int   g_ssrc[EDGES_MAX];
__device__ int   g_bsum[128];

// ---- packed fp32x2 helpers (sm_103a FFMA2) ---------------------------------
__device__ __forceinline__ u64 pk(float lo, float hi) {
    u64 r; asm("mov.b64 %0, {%1, %2};" : "=l"(r) : "f"(lo), "f"(hi)); return r;
}
__device__ __forceinline__ u64 pk1(float v) { return pk(v, v); }
__device__ __forceinline__ u64 ffma2(u64 a, u64 b, u64 c) {
    u64 d; asm("fma.rn.f32x2 %0, %1, %2, %3;" : "=l"(d) : "l"(a), "l"(b), "l"(c));
    return d;
}
__device__ __forceinline__ float2 upk(u64 v) {
    float2 r; asm("mov.b64 {%0, %1}, %2;" : "=f"(r.x), "=f"(r.y) : "l"(v)); return r;
}

// ---------------------------------------------------------------------------
// Degree histogram pipeline: clear -> hist -> 3-step exclusive scan -> sort
// ---------------------------------------------------------------------------
__global__ void clear_cnt_kernel(int n) {
    int i = blockIdx.x * blockDim.x + threadIdx.x;
    if (i < n) g_cnt[i] = 0;
}

__global__ void deg_kernel(const int* __restrict__ dst, int E) {
    int i = blockIdx.x * blockDim.x + threadIdx.x;
    if (i < E) atomicAdd(&g_cnt[dst[i]], 1);
}

// scan step 1: per-block (1024 counts) sums
__global__ void scan1_kernel(int n) {
    __shared__ int wsum[8];
    int b = blockIdx.x, tid = threadIdx.x;
    int i = b * 1024 + tid * 4;
    int s = 0;
    #pragma unroll
    for (int j = 0; j < 4; j++) if (i + j < n) s += g_cnt[i + j];
    #pragma unroll
    for (int o = 16; o > 0; o >>= 1) s += __shfl_down_sync(0xffffffffu, s, o);
    if ((tid & 31) == 0) wsum[tid >> 5] = s;
    __syncthreads();
    if (tid == 0) {
        int t = 0;
        #pragma unroll
        for (int k = 0; k < 8; k++) t += wsum[k];
        g_bsum[b] = t;
    }
}

// scan step 2: exclusive scan of <=128 block sums (single block)
__global__ void scan2_kernel(int nb, int n) {
    __shared__ int sm_[128];
    int tid = threadIdx.x;
    int v = (tid < nb) ? g_bsum[tid] : 0;
    sm_[tid] = v;
    __syncthreads();
    #pragma unroll
    for (int o = 1; o < 128; o <<= 1) {
        int t = (tid >= o) ? sm_[tid - o] : 0;
        __syncthreads();
        sm_[tid] += t;
        __syncthreads();
    }
    if (tid < nb) g_bsum[tid] = sm_[tid] - v;   // exclusive
    if (tid == 127) g_off[n] = sm_[127];        // total = E
}

// scan step 3: full exclusive scan; writes g_off and g_fill
__global__ void scan3_kernel(int n) {
    __shared__ int wsum[8];
    int b = blockIdx.x, tid = threadIdx.x;
    int lane = tid & 31, w = tid >> 5;
    int i = b * 1024 + tid * 4;
    int c[4];
    #pragma unroll
    for (int j = 0; j < 4; j++) c[j] = (i + j < n) ? g_cnt[i + j] : 0;
    int tsum = c[0] + c[1] + c[2] + c[3];
    int v = tsum;
    #pragma unroll
    for (int o = 1; o < 32; o <<= 1) {
        int t = __shfl_up_sync(0xffffffffu, v, o);
        if (lane >= o) v += t;
    }
    if (lane == 31) wsum[w] = v;
    __syncthreads();
    if (tid == 0) {
        int r = 0;
        #pragma unroll
        for (int k = 0; k < 8; k++) { int t = wsum[k]; wsum[k] = r; r += t; }
    }
    __syncthreads();
    int excl = g_bsum[b] + wsum[w] + (v - tsum);
    #pragma unroll
    for (int j = 0; j < 4; j++) {
        if (i + j < n) { g_off[i + j] = excl; g_fill[i + j] = excl; }
        excl += c[j];
    }
}

// bucket edges by destination (order within bucket irrelevant for the sum)
__global__ void sort_kernel(const int* __restrict__ src,
                            const int* __restrict__ dst, int E) {
    int e = blockIdx.x * blockDim.x + threadIdx.x;
    if (e < E) {
        int pos = atomicAdd(&g_fill[dst[e]], 1);
        g_ssrc[pos] = src[e];
    }
}

// ---------------------------------------------------------------------------
// Segment mean-aggregation: one warp per node, register accumulation.
// Replaces zero + red.global scatter: 819MB L2 RMW -> 51MB streamed write.
// ---------------------------------------------------------------------------
__global__ void agg_kernel(const float* __restrict__ h, int n) {
    int node = (blockIdx.x * blockDim.x + threadIdx.x) >> 5;
    int lane = threadIdx.x & 31;
    if (node >= n) return;
    int beg = g_off[node], end = g_off[node + 1];
    const float4* h4 = reinterpret_cast<const float4*>(h);
    float4 acc = make_float4(0.f, 0.f, 0.f, 0.f);
    for (int p = beg; p < end; p += 32) {
        int m = min(32, end - p);
        int s = (lane < m) ? __ldg(g_ssrc + p + lane) : 0;
        #pragma unroll 4
        for (int j = 0; j < m; j++) {
            int sj = __shfl_sync(0xffffffffu, s, j);
            float4 v = __ldg(h4 + (size_t)sj * C4 + lane);
            acc.x += v.x; acc.y += v.y; acc.z += v.z; acc.w += v.w;
        }
    }
    float iv = 1.0f / (float)max(end - beg, 1);
    acc.x *= iv; acc.y *= iv; acc.z *= iv; acc.w *= iv;
    reinterpret_cast<float4*>(g_agg)[(size_t)node * C4 + lane] = acc;
}

// ---------------------------------------------------------------------------
// Fused SAGE dense layer with packed FFMA2:
//   out[n,:] = relu( mean[n,:] @ Wl + in[n,:] @ Wr + bias )
// 64-node tile/block; thread = 8 nodes x 4 cols. Weights in smem, pre-packed
// as u64 col-pair planes (conflict-free LDS.64, no pack ops in the mainloop).
// ---------------------------------------------------------------------------
__global__ void __launch_bounds__(256, 1)
sage_kernel(const float* __restrict__ in,  const float* __restrict__ Wl,
            const float* __restrict__ Wr,  const float* __restrict__ bias,
            float* __restrict__ out, int n)
{
    extern __shared__ char smraw[];
    u64*    sWlA = reinterpret_cast<u64*>(smraw);      // [128k][32c4] cols {0,1}
    u64*    sWlB = sWlA + 4096;                        // cols {2,3}
    u64*    sWrA = sWlB + 4096;
    u64*    sWrB = sWrA + 4096;                        // 128KB weights
    float4* sA   = reinterpret_cast<float4*>(sWrB + 4096); // 64x32 mean
    float4* sB   = sA + 2048;                          // 64x32 root  (+64KB)

    const int tid = threadIdx.x;
    const float4* Wl4 = reinterpret_cast<const float4*>(Wl);
    const float4* Wr4 = reinterpret_cast<const float4*>(Wr);
    #pragma unroll 4
    for (int i = tid; i < 4096; i += 256) {
        float4 l = __ldg(Wl4 + i), r = __ldg(Wr4 + i);
        sWlA[i] = pk(l.x, l.y); sWlB[i] = pk(l.z, l.w);
        sWrA[i] = pk(r.x, r.y); sWrB[i] = pk(r.z, r.w);
    }

    const int n0 = blockIdx.x * 64;
    const float4* agg4 = reinterpret_cast<const float4*>(g_agg);
    const float4* in4  = reinterpret_cast<const float4*>(in);
    #pragma unroll 2
    for (int i = tid; i < 2048; i += 256) {
        int node = n0 + (i >> 5);
        float4 a = make_float4(0.f, 0.f, 0.f, 0.f), b = a;
        if (node < n) {
            a = agg4[(size_t)node * C4 + (i & 31)];
            b = __ldg(in4 + (size_t)node * C4 + (i & 31));
        }
        sA[i] = a; sB[i] = b;
    }
    __syncthreads();

    const int col4 = tid & 31;
    const int nb   = (tid >> 5) * 8;

    u64 acc[8][2];
    #pragma unroll
    for (int m = 0; m < 8; m++) { acc[m][0] = 0ull; acc[m][1] = 0ull; }

    #pragma unroll 2
    for (int k4 = 0; k4 < 32; k4++) {
        float a_[8][4], b_[8][4];
        #pragma unroll
        for (int m = 0; m < 8; m++) {
            *reinterpret_cast<float4*>(a_[m]) = sA[(nb + m) * 32 + k4];
            *reinterpret_cast<float4*>(b_[m]) = sB[(nb + m) * 32 + k4];
        }
        #pragma unroll
        for (int kk = 0; kk < 4; kk++) {
            int k = k4 * 4 + kk;
            u64 wlA = sWlA[k * 32 + col4], wlB = sWlB[k * 32 + col4];
            u64 wrA = sWrA[k * 32 + col4], wrB = sWrB[k * 32 + col4];
            #pragma unroll
            for (int m = 0; m < 8; m++) {
                u64 av = pk1(a_[m][kk]);
                u64 bv = pk1(b_[m][kk]);
                acc[m][0] = ffma2(av, wlA, acc[m][0]);
                acc[m][0] = ffma2(bv, wrA, acc[m][0]);
                acc[m][1] = ffma2(av, wlB, acc[m][1]);
                acc[m][1] = ffma2(bv, wrB, acc[m][1]);
            }
        }
    }

    float4 bq = __ldg(reinterpret_cast<const float4*>(bias) + col4);
    float4* out4 = reinterpret_cast<float4*>(out);
    #pragma unroll
    for (int m = 0; m < 8; m++) {
        int node = n0 + nb + m;
        if (node < n) {
            float2 p0 = upk(acc[m][0]), p1 = upk(acc[m][1]);
            float4 r;
            r.x = fmaxf(p0.x + bq.x, 0.f);
            r.y = fmaxf(p0.y + bq.y, 0.f);
            r.z = fmaxf(p1.x + bq.z, 0.f);
            r.w = fmaxf(p1.y + bq.w, 0.f);
            out4[(size_t)node * C4 + col4] = r;
        }
    }
}

// ---------------------------------------------------------------------------
// Decoder + residual with packed FFMA2:
//   out[n,:] = alpha * (h2[n,:] @ Wd + bd) + (1-alpha) * x[n,:]
// ---------------------------------------------------------------------------
__global__ void __launch_bounds__(256, 1)
dec_kernel(const float* __restrict__ x, const float* __restrict__ Wd,
           const float* __restrict__ bd, const float* __restrict__ alpha_p,
           float* __restrict__ out, int n)
{
    extern __shared__ char smraw[];
    u64*    sWA = reinterpret_cast<u64*>(smraw);   // 4096
    u64*    sWB = sWA + 4096;                      // 4096 (64KB)
    float4* sB  = reinterpret_cast<float4*>(sWB + 4096); // 2048 (32KB)

    const int tid = threadIdx.x;
    const float4* W4 = reinterpret_cast<const float4*>(Wd);
    #pragma unroll 4
    for (int i = tid; i < 4096; i += 256) {
        float4 w = __ldg(W4 + i);
        sWA[i] = pk(w.x, w.y); sWB[i] = pk(w.z, w.w);
    }

    const int n0 = blockIdx.x * 64;
    const float4* h4 = reinterpret_cast<const float4*>(g_h2);
    #pragma unroll 2
    for (int i = tid; i < 2048; i += 256) {
        int node = n0 + (i >> 5);
        sB[i] = (node < n) ? h4[(size_t)node * C4 + (i & 31)]
                           : make_float4(0.f, 0.f, 0.f, 0.f);
    }
    __syncthreads();

    const int col4 = tid & 31;
    const int nb   = (tid >> 5) * 8;

    u64 acc[8][2];
    #pragma unroll
    for (int m = 0; m < 8; m++) { acc[m][0] = 0ull; acc[m][1] = 0ull; }

    #pragma unroll 2
    for (int k4 = 0; k4 < 32; k4++) {
        float b_[8][4];
        #pragma unroll
        for (int m = 0; m < 8; m++)
            *reinterpret_cast<float4*>(b_[m]) = sB[(nb + m) * 32 + k4];
        #pragma unroll
        for (int kk = 0; kk < 4; kk++) {
            int k = k4 * 4 + kk;
            u64 wA = sWA[k * 32 + col4], wB = sWB[k * 32 + col4];
            #pragma unroll
            for (int m = 0; m < 8; m++) {
                u64 bv = pk1(b_[m][kk]);
                acc[m][0] = ffma2(bv, wA, acc[m][0]);
                acc[m][1] = ffma2(bv, wB, acc[m][1]);
            }
        }
    }

    float alpha = __ldg(alpha_p);
    float beta  = 1.0f - alpha;
    float4 bq = __ldg(reinterpret_cast<const float4*>(bd) + col4);
    const float4* x4 = reinterpret_cast<const float4*>(x);
    float4* out4 = reinterpret_cast<float4*>(out);
    #pragma unroll
    for (int m = 0; m < 8; m++) {
        int node = n0 + nb + m;
        if (node < n) {
            float2 p0 = upk(acc[m][0]), p1 = upk(acc[m][1]);
            float4 xv = __ldg(x4 + (size_t)node * C4 + col4);
            float4 r;
            r.x = alpha * (p0.x + bq.x) + beta * xv.x;
            r.y = alpha * (p0.y + bq.y) + beta * xv.y;
            r.z = alpha * (p1.x + bq.z) + beta * xv.z;
            r.w = alpha * (p1.y + bq.w) + beta * xv.w;
            out4[(size_t)node * C4 + col4] = r;
        }
    }
}

// ---------------------------------------------------------------------------
// Host launcher
// ---------------------------------------------------------------------------
extern "C" void kernel_launch(void* const* d_in, const int* in_sizes, int n_in,
                              void* d_out, int out_size)
{
    const float* x   = (const float*)d_in[0];
    const int*   ei  = (const int*)  d_in[1];
    const float* W1l = (const float*)d_in[2];
    const float* b1  = (const float*)d_in[3];
    const float* W1r = (const float*)d_in[4];
    const float* W2l = (const float*)d_in[5];
    const float* b2  = (const float*)d_in[6];
    const float* W2r = (const float*)d_in[7];
    const float* Wd  = (const float*)d_in[8];
    const float* bd  = (const float*)d_in[9];
    const float* al  = (const float*)d_in[10];
    float* out = (float*)d_out;

    const int n = in_sizes[0] / C;
    const int E = in_sizes[1] / 2;
    const int* src = ei;
    const int* dst = ei + E;

    float *h1p = nullptr, *h2p = nullptr;
    cudaGetSymbolAddress((void**)&h1p, g_h1);
    cudaGetSymbolAddress((void**)&h2p, g_h2);

    const int SAGE_SMEM = 16384 * (int)sizeof(u64) + 4096 * (int)sizeof(float4); // 196608
    const int DEC_SMEM  =  8192 * (int)sizeof(u64) + 2048 * (int)sizeof(float4); //  98304
    cudaFuncSetAttribute(sage_kernel, cudaFuncAttributeMaxDynamicSharedMemorySize, SAGE_SMEM);
    cudaFuncSetAttribute(dec_kernel,  cudaFuncAttributeMaxDynamicSharedMemorySize, DEC_SMEM);

    const int nb1   = (n + 1023) / 1024;          // scan blocks (98 for 100K)
    const int egrid = (E + 255) / 256;
    const int agrid = (n * 32 + 255) / 256;       // warp per node
    const int sgrid = (n + 63) / 64;              // 64-node tiles

    // Edge bucketing by dst (built once, used by both layers)
    clear_cnt_kernel<<<(n + 255) / 256, 256>>>(n);
    deg_kernel<<<egrid, 256>>>(dst, E);
    scan1_kernel<<<nb1, 256>>>(n);
    scan2_kernel<<<1, 128>>>(nb1, n);
    scan3_kernel<<<nb1, 256>>>(n);
    sort_kernel<<<egrid, 256>>>(src, dst, E);

    // Layer 1
    agg_kernel<<<agrid, 256>>>(x, n);
    sage_kernel<<<sgrid, 256, SAGE_SMEM>>>(x, W1l, W1r, b1, h1p, n);

    // Layer 2
    agg_kernel<<<agrid, 256>>>(h1p, n);
    sage_kernel<<<sgrid, 256, SAGE_SMEM>>>(h1p, W2l, W2r, b2, h2p, n);

    // Decoder + residual
    dec_kernel<<<sgrid, 256, DEC_SMEM>>>(x, Wd, bd, al, out, n);
}